// round 1
// baseline (speedup 1.0000x reference)
#include <cuda_runtime.h>
#include <cmath>

#define B_   16
#define N_   1024
#define D_   384
#define H_   6
#define DH_  64
#define MTOK (B_ * N_)          // 16384 token rows

// ---------------- scratch (device globals: no allocs allowed) ----------------
__device__ float g_t[MTOK * D_];                         // LN1 output
__device__ float g_qkv[MTOK * 3 * D_];                   // packed q|k|v per token
__device__ float g_scores[(size_t)B_ * H_ * N_ * N_];    // 403 MB attention scores
__device__ float g_o[MTOK * D_];                         // attention out (head-concat)
__device__ float g_y[MTOK * D_];                         // X + attn
__device__ float g_x2[MTOK * D_];                        // LN2 output
__device__ float g_h[MTOK * 2 * D_];                     // MLP hidden

__device__ __forceinline__ float gelu_exact(float x) {
    return 0.5f * x * (1.0f + erff(x * 0.7071067811865475f));
}

// ---------------- LayerNorm: one block (128 threads) per row of D=384 ----------------
__global__ void ln_kernel(const float* __restrict__ x, const float* __restrict__ w,
                          const float* __restrict__ b, float* __restrict__ out) {
    int row = blockIdx.x;
    const float* xr = x + (size_t)row * D_;
    int tid = threadIdx.x;
    float v0 = xr[tid], v1 = xr[tid + 128], v2 = xr[tid + 256];
    float s = v0 + v1 + v2;
    __shared__ float red[4], red2[4];
    #pragma unroll
    for (int o = 16; o > 0; o >>= 1) s += __shfl_xor_sync(0xffffffffu, s, o);
    if ((tid & 31) == 0) red[tid >> 5] = s;
    __syncthreads();
    float mu = (red[0] + red[1] + red[2] + red[3]) * (1.0f / D_);
    float d0 = v0 - mu, d1 = v1 - mu, d2 = v2 - mu;
    float sq = d0 * d0 + d1 * d1 + d2 * d2;
    #pragma unroll
    for (int o = 16; o > 0; o >>= 1) sq += __shfl_xor_sync(0xffffffffu, sq, o);
    if ((tid & 31) == 0) red2[tid >> 5] = sq;
    __syncthreads();
    float var = (red2[0] + red2[1] + red2[2] + red2[3]) * (1.0f / D_);
    float rstd = rsqrtf(var + 1e-5f);
    float* orow = out + (size_t)row * D_;
    orow[tid]       = d0 * rstd * w[tid]       + b[tid];
    orow[tid + 128] = d1 * rstd * w[tid + 128] + b[tid + 128];
    orow[tid + 256] = d2 * rstd * w[tid + 256] + b[tid + 256];
}

// ---------------- Tiled SGEMM, C = alpha * A * W^T (+bias)(+gelu)(+residual) ----------
// A: [M,K] row-major (lda), W: [N,K] row-major (ldw), C: [M,N] (ldc).
// Batched over blockIdx.z with two-level strides: z = b*H + h.
// BM=BN=64, BK=16, 256 threads, 4x4 per thread.
template <int ACT, bool BIAS, bool RES>
__global__ void gemm_nt(const float* __restrict__ A, const float* __restrict__ W,
                        const float* __restrict__ bias, const float* __restrict__ res,
                        float* __restrict__ C,
                        int M, int N, int K, int lda, int ldw, int ldc,
                        long long sAb, long long sAh,
                        long long sWb, long long sWh,
                        long long sCb, long long sCh,
                        float alpha) {
    int bz = blockIdx.z;
    int bb = bz / H_, hh = bz % H_;
    const float* Ab = A + bb * sAb + hh * sAh;
    const float* Wb = W + bb * sWb + hh * sWh;
    float* Cb = C + bb * sCb + hh * sCh;

    int m0 = blockIdx.y * 64, n0 = blockIdx.x * 64;
    __shared__ float As[64][17];
    __shared__ float Ws[64][17];
    float acc[4][4] = {};

    int tid = threadIdx.y * 16 + threadIdx.x;
    int lr = tid >> 2;          // 0..63
    int lc = (tid & 3) * 4;     // 0,4,8,12

    for (int k0 = 0; k0 < K; k0 += 16) {
        float4 a = *(const float4*)(Ab + (size_t)(m0 + lr) * lda + k0 + lc);
        As[lr][lc] = a.x; As[lr][lc + 1] = a.y; As[lr][lc + 2] = a.z; As[lr][lc + 3] = a.w;
        float4 wv = *(const float4*)(Wb + (size_t)(n0 + lr) * ldw + k0 + lc);
        Ws[lr][lc] = wv.x; Ws[lr][lc + 1] = wv.y; Ws[lr][lc + 2] = wv.z; Ws[lr][lc + 3] = wv.w;
        __syncthreads();
        #pragma unroll
        for (int kk = 0; kk < 16; kk++) {
            float ar[4], wr[4];
            #pragma unroll
            for (int i = 0; i < 4; i++) ar[i] = As[threadIdx.y * 4 + i][kk];
            #pragma unroll
            for (int j = 0; j < 4; j++) wr[j] = Ws[threadIdx.x * 4 + j][kk];
            #pragma unroll
            for (int i = 0; i < 4; i++)
                #pragma unroll
                for (int j = 0; j < 4; j++) acc[i][j] += ar[i] * wr[j];
        }
        __syncthreads();
    }

    #pragma unroll
    for (int i = 0; i < 4; i++) {
        int m = m0 + threadIdx.y * 4 + i;
        #pragma unroll
        for (int j = 0; j < 4; j++) {
            int n = n0 + threadIdx.x * 4 + j;
            float v = acc[i][j] * alpha;
            if (BIAS) v += bias[n];
            if (ACT == 1) v = gelu_exact(v);
            if (RES) v += res[(size_t)m * ldc + n];
            Cb[(size_t)m * ldc + n] = v;
        }
    }
}

// ---------------- Tiled SGEMM NN, C = A * B (for P@V), batched over z=b*H+h ----------
template <int DUMMY>
__global__ void gemm_nn(const float* __restrict__ A, const float* __restrict__ Bm,
                        float* __restrict__ C,
                        int M, int N, int K, int lda, int ldb, int ldc,
                        long long sAb, long long sAh,
                        long long sBb, long long sBh,
                        long long sCb, long long sCh) {
    int bz = blockIdx.z;
    int bb = bz / H_, hh = bz % H_;
    const float* Ab = A + bb * sAb + hh * sAh;
    const float* Bb = Bm + bb * sBb + hh * sBh;
    float* Cb = C + bb * sCb + hh * sCh;

    int m0 = blockIdx.y * 64, n0 = blockIdx.x * 64;
    __shared__ float As[64][17];
    __shared__ float Bs[16][64];
    float acc[4][4] = {};

    int tid = threadIdx.y * 16 + threadIdx.x;
    int lr = tid >> 2;
    int lc = (tid & 3) * 4;
    int br = tid >> 4;              // 0..15
    int bc = (tid & 15) * 4;        // 0..60

    for (int k0 = 0; k0 < K; k0 += 16) {
        float4 a = *(const float4*)(Ab + (size_t)(m0 + lr) * lda + k0 + lc);
        As[lr][lc] = a.x; As[lr][lc + 1] = a.y; As[lr][lc + 2] = a.z; As[lr][lc + 3] = a.w;
        float4 bv = *(const float4*)(Bb + (size_t)(k0 + br) * ldb + n0 + bc);
        Bs[br][bc] = bv.x; Bs[br][bc + 1] = bv.y; Bs[br][bc + 2] = bv.z; Bs[br][bc + 3] = bv.w;
        __syncthreads();
        #pragma unroll
        for (int kk = 0; kk < 16; kk++) {
            float ar[4], brv[4];
            #pragma unroll
            for (int i = 0; i < 4; i++) ar[i] = As[threadIdx.y * 4 + i][kk];
            #pragma unroll
            for (int j = 0; j < 4; j++) brv[j] = Bs[kk][threadIdx.x * 4 + j];
            #pragma unroll
            for (int i = 0; i < 4; i++)
                #pragma unroll
                for (int j = 0; j < 4; j++) acc[i][j] += ar[i] * brv[j];
        }
        __syncthreads();
    }

    #pragma unroll
    for (int i = 0; i < 4; i++) {
        int m = m0 + threadIdx.y * 4 + i;
        #pragma unroll
        for (int j = 0; j < 4; j++) {
            int n = n0 + threadIdx.x * 4 + j;
            Cb[(size_t)m * ldc + n] = acc[i][j];
        }
    }
}

// ---------------- Row softmax over 1024 (in place) ----------------
__global__ void softmax_kernel(float* __restrict__ s) {
    size_t row = blockIdx.x;
    float* p = s + row * (size_t)N_;
    int tid = threadIdx.x;  // 256
    float v[4];
    #pragma unroll
    for (int i = 0; i < 4; i++) v[i] = p[tid + i * 256];
    float mx = fmaxf(fmaxf(v[0], v[1]), fmaxf(v[2], v[3]));
    __shared__ float red[8], red2[8];
    #pragma unroll
    for (int o = 16; o > 0; o >>= 1) mx = fmaxf(mx, __shfl_xor_sync(0xffffffffu, mx, o));
    if ((tid & 31) == 0) red[tid >> 5] = mx;
    __syncthreads();
    mx = red[0];
    #pragma unroll
    for (int w = 1; w < 8; w++) mx = fmaxf(mx, red[w]);
    float sum = 0.f;
    #pragma unroll
    for (int i = 0; i < 4; i++) { v[i] = __expf(v[i] - mx); sum += v[i]; }
    #pragma unroll
    for (int o = 16; o > 0; o >>= 1) sum += __shfl_xor_sync(0xffffffffu, sum, o);
    if ((tid & 31) == 0) red2[tid >> 5] = sum;
    __syncthreads();
    sum = red2[0] + red2[1] + red2[2] + red2[3] + red2[4] + red2[5] + red2[6] + red2[7];
    float inv = 1.0f / sum;
    #pragma unroll
    for (int i = 0; i < 4; i++) p[tid + i * 256] = v[i] * inv;
}

// ---------------- launch ----------------
extern "C" void kernel_launch(void* const* d_in, const int* in_sizes, int n_in,
                              void* d_out, int out_size) {
    const float* X    = (const float*)d_in[0];
    const float* Wq   = (const float*)d_in[1];
    const float* Wk   = (const float*)d_in[2];
    const float* Wv   = (const float*)d_in[3];
    const float* Wo   = (const float*)d_in[4];
    const float* bo   = (const float*)d_in[5];
    const float* ln1w = (const float*)d_in[6];
    const float* ln1b = (const float*)d_in[7];
    const float* ln2w = (const float*)d_in[8];
    const float* ln2b = (const float*)d_in[9];
    const float* W1   = (const float*)d_in[10];
    const float* b1   = (const float*)d_in[11];
    const float* W2   = (const float*)d_in[12];
    const float* b2   = (const float*)d_in[13];
    float* out = (float*)d_out;

    float *t, *qkv, *scores, *o, *y, *x2, *h;
    cudaGetSymbolAddress((void**)&t,      g_t);
    cudaGetSymbolAddress((void**)&qkv,    g_qkv);
    cudaGetSymbolAddress((void**)&scores, g_scores);
    cudaGetSymbolAddress((void**)&o,      g_o);
    cudaGetSymbolAddress((void**)&y,      g_y);
    cudaGetSymbolAddress((void**)&x2,     g_x2);
    cudaGetSymbolAddress((void**)&h,      g_h);

    dim3 blk(16, 16);
    const float scale = 0.125f;   // 1/sqrt(64)

    // 1) LN1
    ln_kernel<<<MTOK, 128>>>(X, ln1w, ln1b, t);

    // 2-4) Q, K, V projections into packed qkv [MTOK, 1152]
    {
        dim3 g(D_ / 64, MTOK / 64, 1);
        gemm_nt<0, false, false><<<g, blk>>>(t, Wq, nullptr, nullptr, qkv,
            MTOK, D_, D_, D_, D_, 3 * D_, 0, 0, 0, 0, 0, 0, 1.0f);
        gemm_nt<0, false, false><<<g, blk>>>(t, Wk, nullptr, nullptr, qkv + D_,
            MTOK, D_, D_, D_, D_, 3 * D_, 0, 0, 0, 0, 0, 0, 1.0f);
        gemm_nt<0, false, false><<<g, blk>>>(t, Wv, nullptr, nullptr, qkv + 2 * D_,
            MTOK, D_, D_, D_, D_, 3 * D_, 0, 0, 0, 0, 0, 0, 1.0f);
    }

    // 5) scores[b,h] = (Q Kᵀ) * scale   — batched over z = b*H + h
    {
        dim3 g(N_ / 64, N_ / 64, B_ * H_);
        gemm_nt<0, false, false><<<g, blk>>>(qkv, qkv + D_, nullptr, nullptr, scores,
            N_, N_, DH_, 3 * D_, 3 * D_, N_,
            (long long)N_ * 3 * D_, DH_,
            (long long)N_ * 3 * D_, DH_,
            (long long)H_ * N_ * N_, (long long)N_ * N_,
            scale);
    }

    // 6) softmax rows
    softmax_kernel<<<B_ * H_ * N_, 256>>>(scores);

    // 7) O[b,h] = P V  (written head-concat into g_o [MTOK, 384])
    {
        dim3 g(DH_ / 64, N_ / 64, B_ * H_);
        gemm_nn<0><<<g, blk>>>(scores, qkv + 2 * D_, o,
            N_, DH_, N_, N_, 3 * D_, D_,
            (long long)H_ * N_ * N_, (long long)N_ * N_,
            (long long)N_ * 3 * D_, DH_,
            (long long)N_ * D_, DH_);
    }

    // 8) y = X + (o @ Woᵀ + bo)
    {
        dim3 g(D_ / 64, MTOK / 64, 1);
        gemm_nt<0, true, true><<<g, blk>>>(o, Wo, bo, X, y,
            MTOK, D_, D_, D_, D_, D_, 0, 0, 0, 0, 0, 0, 1.0f);
    }

    // 9) LN2
    ln_kernel<<<MTOK, 128>>>(y, ln2w, ln2b, x2);

    // 10) h = gelu(x2 @ W1ᵀ + b1)
    {
        dim3 g(2 * D_ / 64, MTOK / 64, 1);
        gemm_nt<1, true, false><<<g, blk>>>(x2, W1, b1, nullptr, h,
            MTOK, 2 * D_, D_, D_, D_, 2 * D_, 0, 0, 0, 0, 0, 0, 1.0f);
    }

    // 11) out = x2 + (h @ W2ᵀ + b2)
    {
        dim3 g(D_ / 64, MTOK / 64, 1);
        gemm_nt<0, true, true><<<g, blk>>>(h, W2, b2, x2, out,
            MTOK, D_, 2 * D_, 2 * D_, 2 * D_, D_, 0, 0, 0, 0, 0, 0, 1.0f);
    }
}

// round 2
// speedup vs baseline: 1.5992x; 1.5992x over previous
#include <cuda_runtime.h>
#include <cmath>

#define B_   16
#define N_   1024
#define D_   384
#define H_   6
#define DH_  64
#define MTOK (B_ * N_)          // 16384 token rows

// ---------------- scratch (device globals: no allocs allowed) ----------------
__device__ float g_t[MTOK * D_];                         // LN1 output
__device__ float g_qkv[MTOK * 3 * D_];                   // packed q|k|v per token
__device__ float g_scores[(size_t)B_ * H_ * N_ * N_];    // 403 MB attention scores
__device__ float g_o[MTOK * D_];                         // attention out (head-concat)
__device__ float g_y[MTOK * D_];                         // X + attn
__device__ float g_x2[MTOK * D_];                        // LN2 output
__device__ float g_h[MTOK * 2 * D_];                     // MLP hidden

__device__ __forceinline__ float gelu_exact(float x) {
    return 0.5f * x * (1.0f + erff(x * 0.7071067811865475f));
}

__device__ __forceinline__ unsigned f2tf32(float f) {
    unsigned u;
    asm volatile("cvt.rna.tf32.f32 %0, %1;" : "=r"(u) : "f"(f));
    return u;
}

__device__ __forceinline__ void mma_tf32(float* c, unsigned a0, unsigned a1,
                                         unsigned a2, unsigned a3,
                                         unsigned b0, unsigned b1) {
    asm volatile(
        "mma.sync.aligned.m16n8k8.row.col.f32.tf32.tf32.f32 "
        "{%0,%1,%2,%3}, {%4,%5,%6,%7}, {%8,%9}, {%0,%1,%2,%3};\n"
        : "+f"(c[0]), "+f"(c[1]), "+f"(c[2]), "+f"(c[3])
        : "r"(a0), "r"(a1), "r"(a2), "r"(a3), "r"(b0), "r"(b1));
}

// ---------------- LayerNorm: one block (128 threads) per row of D=384 ----------------
__global__ void ln_kernel(const float* __restrict__ x, const float* __restrict__ w,
                          const float* __restrict__ b, float* __restrict__ out) {
    int row = blockIdx.x;
    const float* xr = x + (size_t)row * D_;
    int tid = threadIdx.x;
    float v0 = xr[tid], v1 = xr[tid + 128], v2 = xr[tid + 256];
    float s = v0 + v1 + v2;
    __shared__ float red[4], red2[4];
    #pragma unroll
    for (int o = 16; o > 0; o >>= 1) s += __shfl_xor_sync(0xffffffffu, s, o);
    if ((tid & 31) == 0) red[tid >> 5] = s;
    __syncthreads();
    float mu = (red[0] + red[1] + red[2] + red[3]) * (1.0f / D_);
    float d0 = v0 - mu, d1 = v1 - mu, d2 = v2 - mu;
    float sq = d0 * d0 + d1 * d1 + d2 * d2;
    #pragma unroll
    for (int o = 16; o > 0; o >>= 1) sq += __shfl_xor_sync(0xffffffffu, sq, o);
    if ((tid & 31) == 0) red2[tid >> 5] = sq;
    __syncthreads();
    float var = (red2[0] + red2[1] + red2[2] + red2[3]) * (1.0f / D_);
    float rstd = rsqrtf(var + 1e-5f);
    float* orow = out + (size_t)row * D_;
    orow[tid]       = d0 * rstd * w[tid]       + b[tid];
    orow[tid + 128] = d1 * rstd * w[tid + 128] + b[tid + 128];
    orow[tid + 256] = d2 * rstd * w[tid + 256] + b[tid + 256];
}

// ======================= TF32 tensor-core GEMM, NT =======================
// C = alpha * A * W^T (+bias)(+gelu)(+residual)
// A: [M,K] row-major (lda), W: [N,K] row-major (ldw), C: [M,N] (ldc).
// Block tile: BM = WM*64, BN = WN*32, BK=16. Warp tile 64x32 (4x4 m16n8k8 frags).
template <int WM, int WN, int ACT, bool BIAS, bool RES>
__global__ void gemm_nt_tc(const float* __restrict__ A, const float* __restrict__ W,
                           const float* __restrict__ bias, const float* __restrict__ res,
                           float* __restrict__ C,
                           int K, int lda, int ldw, int ldc,
                           long long sAb, long long sAh,
                           long long sWb, long long sWh,
                           long long sCb, long long sCh,
                           float alpha) {
    constexpr int BM = WM * 64, BN = WN * 32, NTHR = WM * WN * 32;
    constexpr int SS = 20;                       // smem row stride (conflict-free)
    __shared__ unsigned sA[BM * SS];
    __shared__ unsigned sW[BN * SS];

    int bz = blockIdx.z;
    int bb = bz / H_, hh = bz % H_;
    const float* Ab = A + bb * sAb + hh * sAh;
    const float* Wb = W + bb * sWb + hh * sWh;
    float* Cb = C + bb * sCb + hh * sCh;

    int m0 = blockIdx.y * BM, n0 = blockIdx.x * BN;
    int tid = threadIdx.x;
    int lane = tid & 31, wid = tid >> 5;
    int wm = wid % WM, wn = wid / WM;
    int g = lane >> 2, t = lane & 3;

    float acc[4][4][4] = {};

    for (int k0 = 0; k0 < K; k0 += 16) {
        // ---- stage A and W tiles (tf32-rounded) ----
        #pragma unroll
        for (int f = tid; f < (BM + BN) * 4; f += NTHR) {
            if (f < BM * 4) {
                int row = f >> 2, c4 = (f & 3) * 4;
                float4 v = *(const float4*)(Ab + (size_t)(m0 + row) * lda + k0 + c4);
                unsigned* d = sA + row * SS + c4;
                d[0] = f2tf32(v.x); d[1] = f2tf32(v.y);
                d[2] = f2tf32(v.z); d[3] = f2tf32(v.w);
            } else {
                int f2 = f - BM * 4;
                int row = f2 >> 2, c4 = (f2 & 3) * 4;
                float4 v = *(const float4*)(Wb + (size_t)(n0 + row) * ldw + k0 + c4);
                unsigned* d = sW + row * SS + c4;
                d[0] = f2tf32(v.x); d[1] = f2tf32(v.y);
                d[2] = f2tf32(v.z); d[3] = f2tf32(v.w);
            }
        }
        __syncthreads();

        #pragma unroll
        for (int ks = 0; ks < 16; ks += 8) {
            unsigned a[4][4], b[4][2];
            #pragma unroll
            for (int mf = 0; mf < 4; mf++) {
                int r = wm * 64 + mf * 16 + g;
                const unsigned* p = sA + r * SS + ks + t;
                a[mf][0] = p[0];
                a[mf][1] = p[8 * SS];
                a[mf][2] = p[4];
                a[mf][3] = p[8 * SS + 4];
            }
            #pragma unroll
            for (int nf = 0; nf < 4; nf++) {
                int n = wn * 32 + nf * 8 + g;
                const unsigned* p = sW + n * SS + ks + t;
                b[nf][0] = p[0];
                b[nf][1] = p[4];
            }
            #pragma unroll
            for (int mf = 0; mf < 4; mf++)
                #pragma unroll
                for (int nf = 0; nf < 4; nf++)
                    mma_tf32(acc[mf][nf], a[mf][0], a[mf][1], a[mf][2], a[mf][3],
                             b[nf][0], b[nf][1]);
        }
        __syncthreads();
    }

    // ---- epilogue ----
    #pragma unroll
    for (int mf = 0; mf < 4; mf++) {
        int r0 = m0 + wm * 64 + mf * 16 + g;
        #pragma unroll
        for (int nf = 0; nf < 4; nf++) {
            int c = n0 + wn * 32 + nf * 8 + 2 * t;
            float v0 = acc[mf][nf][0] * alpha, v1 = acc[mf][nf][1] * alpha;
            float v2 = acc[mf][nf][2] * alpha, v3 = acc[mf][nf][3] * alpha;
            if (BIAS) {
                float b0v = bias[c], b1v = bias[c + 1];
                v0 += b0v; v1 += b1v; v2 += b0v; v3 += b1v;
            }
            if (ACT == 1) {
                v0 = gelu_exact(v0); v1 = gelu_exact(v1);
                v2 = gelu_exact(v2); v3 = gelu_exact(v3);
            }
            if (RES) {
                v0 += res[(size_t)r0 * ldc + c];
                v1 += res[(size_t)r0 * ldc + c + 1];
                v2 += res[(size_t)(r0 + 8) * ldc + c];
                v3 += res[(size_t)(r0 + 8) * ldc + c + 1];
            }
            *(float2*)(Cb + (size_t)r0 * ldc + c)       = make_float2(v0, v1);
            *(float2*)(Cb + (size_t)(r0 + 8) * ldc + c) = make_float2(v2, v3);
        }
    }
}

// ======================= TF32 tensor-core GEMM, NN (P @ V) =======================
// A: [M,K] row-major (lda), B: [K,N] row-major (ldb), C: [M,N] (ldc).
template <int WM, int WN>
__global__ void gemm_nn_tc(const float* __restrict__ A, const float* __restrict__ Bm,
                           float* __restrict__ C,
                           int K, int lda, int ldb, int ldc,
                           long long sAb, long long sAh,
                           long long sBb, long long sBh,
                           long long sCb, long long sCh) {
    constexpr int BM = WM * 64, BN = WN * 32, NTHR = WM * WN * 32;
    constexpr int SS = 20;          // A tile stride
    constexpr int SB = BN + 8;      // B tile stride (conflict-free for 8k+n pattern)
    constexpr int BN4 = BN / 4;
    __shared__ unsigned sA[BM * SS];
    __shared__ unsigned sB[16 * SB];

    int bz = blockIdx.z;
    int bb = bz / H_, hh = bz % H_;
    const float* Ab = A + bb * sAb + hh * sAh;
    const float* Bb = Bm + bb * sBb + hh * sBh;
    float* Cb = C + bb * sCb + hh * sCh;

    int m0 = blockIdx.y * BM, n0 = blockIdx.x * BN;
    int tid = threadIdx.x;
    int lane = tid & 31, wid = tid >> 5;
    int wm = wid % WM, wn = wid / WM;
    int g = lane >> 2, t = lane & 3;

    float acc[4][4][4] = {};

    for (int k0 = 0; k0 < K; k0 += 16) {
        #pragma unroll
        for (int f = tid; f < BM * 4 + 16 * BN4; f += NTHR) {
            if (f < BM * 4) {
                int row = f >> 2, c4 = (f & 3) * 4;
                float4 v = *(const float4*)(Ab + (size_t)(m0 + row) * lda + k0 + c4);
                unsigned* d = sA + row * SS + c4;
                d[0] = f2tf32(v.x); d[1] = f2tf32(v.y);
                d[2] = f2tf32(v.z); d[3] = f2tf32(v.w);
            } else {
                int f2 = f - BM * 4;
                int row = f2 / BN4, c4 = (f2 % BN4) * 4;
                float4 v = *(const float4*)(Bb + (size_t)(k0 + row) * ldb + n0 + c4);
                unsigned* d = sB + row * SB + c4;
                d[0] = f2tf32(v.x); d[1] = f2tf32(v.y);
                d[2] = f2tf32(v.z); d[3] = f2tf32(v.w);
            }
        }
        __syncthreads();

        #pragma unroll
        for (int ks = 0; ks < 16; ks += 8) {
            unsigned a[4][4], b[4][2];
            #pragma unroll
            for (int mf = 0; mf < 4; mf++) {
                int r = wm * 64 + mf * 16 + g;
                const unsigned* p = sA + r * SS + ks + t;
                a[mf][0] = p[0];
                a[mf][1] = p[8 * SS];
                a[mf][2] = p[4];
                a[mf][3] = p[8 * SS + 4];
            }
            #pragma unroll
            for (int nf = 0; nf < 4; nf++) {
                int n = wn * 32 + nf * 8 + g;
                b[nf][0] = sB[(ks + t) * SB + n];
                b[nf][1] = sB[(ks + t + 4) * SB + n];
            }
            #pragma unroll
            for (int mf = 0; mf < 4; mf++)
                #pragma unroll
                for (int nf = 0; nf < 4; nf++)
                    mma_tf32(acc[mf][nf], a[mf][0], a[mf][1], a[mf][2], a[mf][3],
                             b[nf][0], b[nf][1]);
        }
        __syncthreads();
    }

    #pragma unroll
    for (int mf = 0; mf < 4; mf++) {
        int r0 = m0 + wm * 64 + mf * 16 + g;
        #pragma unroll
        for (int nf = 0; nf < 4; nf++) {
            int c = n0 + wn * 32 + nf * 8 + 2 * t;
            *(float2*)(Cb + (size_t)r0 * ldc + c) =
                make_float2(acc[mf][nf][0], acc[mf][nf][1]);
            *(float2*)(Cb + (size_t)(r0 + 8) * ldc + c) =
                make_float2(acc[mf][nf][2], acc[mf][nf][3]);
        }
    }
}

// ---------------- Row softmax over 1024 (in place) ----------------
__global__ void softmax_kernel(float* __restrict__ s) {
    size_t row = blockIdx.x;
    float* p = s + row * (size_t)N_;
    int tid = threadIdx.x;  // 256
    float v[4];
    #pragma unroll
    for (int i = 0; i < 4; i++) v[i] = p[tid + i * 256];
    float mx = fmaxf(fmaxf(v[0], v[1]), fmaxf(v[2], v[3]));
    __shared__ float red[8], red2[8];
    #pragma unroll
    for (int o = 16; o > 0; o >>= 1) mx = fmaxf(mx, __shfl_xor_sync(0xffffffffu, mx, o));
    if ((tid & 31) == 0) red[tid >> 5] = mx;
    __syncthreads();
    mx = red[0];
    #pragma unroll
    for (int w = 1; w < 8; w++) mx = fmaxf(mx, red[w]);
    float sum = 0.f;
    #pragma unroll
    for (int i = 0; i < 4; i++) { v[i] = __expf(v[i] - mx); sum += v[i]; }
    #pragma unroll
    for (int o = 16; o > 0; o >>= 1) sum += __shfl_xor_sync(0xffffffffu, sum, o);
    if ((tid & 31) == 0) red2[tid >> 5] = sum;
    __syncthreads();
    sum = red2[0] + red2[1] + red2[2] + red2[3] + red2[4] + red2[5] + red2[6] + red2[7];
    float inv = 1.0f / sum;
    #pragma unroll
    for (int i = 0; i < 4; i++) p[tid + i * 256] = v[i] * inv;
}

// ---------------- launch ----------------
extern "C" void kernel_launch(void* const* d_in, const int* in_sizes, int n_in,
                              void* d_out, int out_size) {
    const float* X    = (const float*)d_in[0];
    const float* Wq   = (const float*)d_in[1];
    const float* Wk   = (const float*)d_in[2];
    const float* Wv   = (const float*)d_in[3];
    const float* Wo   = (const float*)d_in[4];
    const float* bo   = (const float*)d_in[5];
    const float* ln1w = (const float*)d_in[6];
    const float* ln1b = (const float*)d_in[7];
    const float* ln2w = (const float*)d_in[8];
    const float* ln2b = (const float*)d_in[9];
    const float* W1   = (const float*)d_in[10];
    const float* b1   = (const float*)d_in[11];
    const float* W2   = (const float*)d_in[12];
    const float* b2   = (const float*)d_in[13];
    float* out = (float*)d_out;

    float *t, *qkv, *scores, *o, *y, *x2, *h;
    cudaGetSymbolAddress((void**)&t,      g_t);
    cudaGetSymbolAddress((void**)&qkv,    g_qkv);
    cudaGetSymbolAddress((void**)&scores, g_scores);
    cudaGetSymbolAddress((void**)&o,      g_o);
    cudaGetSymbolAddress((void**)&y,      g_y);
    cudaGetSymbolAddress((void**)&x2,     g_x2);
    cudaGetSymbolAddress((void**)&h,      g_h);

    const float scale = 0.125f;   // 1/sqrt(64)

    // 1) LN1
    ln_kernel<<<MTOK, 128>>>(X, ln1w, ln1b, t);

    // 2-4) Q, K, V projections into packed qkv [MTOK, 1152]
    {
        dim3 g(D_ / 128, MTOK / 128, 1);
        gemm_nt_tc<2, 4, 0, false, false><<<g, 256>>>(t, Wq, nullptr, nullptr, qkv,
            D_, D_, D_, 3 * D_, 0, 0, 0, 0, 0, 0, 1.0f);
        gemm_nt_tc<2, 4, 0, false, false><<<g, 256>>>(t, Wk, nullptr, nullptr, qkv + D_,
            D_, D_, D_, 3 * D_, 0, 0, 0, 0, 0, 0, 1.0f);
        gemm_nt_tc<2, 4, 0, false, false><<<g, 256>>>(t, Wv, nullptr, nullptr, qkv + 2 * D_,
            D_, D_, D_, 3 * D_, 0, 0, 0, 0, 0, 0, 1.0f);
    }

    // 5) scores[b,h] = (Q Kᵀ) * scale   — batched over z = b*H + h
    {
        dim3 g(N_ / 128, N_ / 128, B_ * H_);
        gemm_nt_tc<2, 4, 0, false, false><<<g, 256>>>(qkv, qkv + D_, nullptr, nullptr, scores,
            DH_, 3 * D_, 3 * D_, N_,
            (long long)N_ * 3 * D_, DH_,
            (long long)N_ * 3 * D_, DH_,
            (long long)H_ * N_ * N_, (long long)N_ * N_,
            scale);
    }

    // 6) softmax rows
    softmax_kernel<<<B_ * H_ * N_, 256>>>(scores);

    // 7) O[b,h] = P V  (written head-concat into g_o [MTOK, 384])
    {
        dim3 g(DH_ / 64, N_ / 128, B_ * H_);
        gemm_nn_tc<2, 2><<<g, 128>>>(scores, qkv + 2 * D_, o,
            N_, N_, 3 * D_, D_,
            (long long)H_ * N_ * N_, (long long)N_ * N_,
            (long long)N_ * 3 * D_, DH_,
            (long long)N_ * D_, DH_);
    }

    // 8) y = X + (o @ Woᵀ + bo)
    {
        dim3 g(D_ / 128, MTOK / 128, 1);
        gemm_nt_tc<2, 4, 0, true, true><<<g, 256>>>(o, Wo, bo, X, y,
            D_, D_, D_, D_, 0, 0, 0, 0, 0, 0, 1.0f);
    }

    // 9) LN2
    ln_kernel<<<MTOK, 128>>>(y, ln2w, ln2b, x2);

    // 10) h = gelu(x2 @ W1ᵀ + b1)
    {
        dim3 g(2 * D_ / 128, MTOK / 128, 1);
        gemm_nt_tc<2, 4, 1, true, false><<<g, 256>>>(x2, W1, b1, nullptr, h,
            D_, D_, D_, 2 * D_, 0, 0, 0, 0, 0, 0, 1.0f);
    }

    // 11) out = x2 + (h @ W2ᵀ + b2)
    {
        dim3 g(D_ / 128, MTOK / 128, 1);
        gemm_nt_tc<2, 4, 0, true, true><<<g, 256>>>(h, W2, b2, x2, out,
            2 * D_, 2 * D_, 2 * D_, D_, 0, 0, 0, 0, 0, 0, 1.0f);
    }
}

// round 3
// speedup vs baseline: 3.4044x; 2.1288x over previous
#include <cuda_runtime.h>
#include <cmath>

#define B_   16
#define N_   1024
#define D_   384
#define H_   6
#define DH_  64
#define MTOK (B_ * N_)          // 16384 token rows

// ---------------- scratch (device globals: no allocs allowed) ----------------
__device__ float g_t[MTOK * D_];                         // LN1 output
__device__ float g_qkv[MTOK * 3 * D_];                   // packed q|k|v per token
__device__ float g_o[MTOK * D_];                         // attention out (head-concat)
__device__ float g_y[MTOK * D_];                         // X + attn
__device__ float g_x2[MTOK * D_];                        // LN2 output
__device__ float g_h[MTOK * 2 * D_];                     // MLP hidden

__device__ __forceinline__ float gelu_exact(float x) {
    return 0.5f * x * (1.0f + erff(x * 0.7071067811865475f));
}

__device__ __forceinline__ unsigned f2tf32(float f) {
    unsigned u;
    asm volatile("cvt.rna.tf32.f32 %0, %1;" : "=r"(u) : "f"(f));
    return u;
}

__device__ __forceinline__ void mma_tf32(float* c, unsigned a0, unsigned a1,
                                         unsigned a2, unsigned a3,
                                         unsigned b0, unsigned b1) {
    asm volatile(
        "mma.sync.aligned.m16n8k8.row.col.f32.tf32.tf32.f32 "
        "{%0,%1,%2,%3}, {%4,%5,%6,%7}, {%8,%9}, {%0,%1,%2,%3};\n"
        : "+f"(c[0]), "+f"(c[1]), "+f"(c[2]), "+f"(c[3])
        : "r"(a0), "r"(a1), "r"(a2), "r"(a3), "r"(b0), "r"(b1));
}

__device__ __forceinline__ void cp16(void* s, const void* g) {
    unsigned sa = (unsigned)__cvta_generic_to_shared(s);
    asm volatile("cp.async.ca.shared.global [%0], [%1], 16;" :: "r"(sa), "l"(g));
}

// ---------------- LayerNorm: one block (128 threads) per row of D=384 ----------------
__global__ void ln_kernel(const float* __restrict__ x, const float* __restrict__ w,
                          const float* __restrict__ b, float* __restrict__ out) {
    int row = blockIdx.x;
    const float* xr = x + (size_t)row * D_;
    int tid = threadIdx.x;
    float v0 = xr[tid], v1 = xr[tid + 128], v2 = xr[tid + 256];
    float s = v0 + v1 + v2;
    __shared__ float red[4], red2[4];
    #pragma unroll
    for (int o = 16; o > 0; o >>= 1) s += __shfl_xor_sync(0xffffffffu, s, o);
    if ((tid & 31) == 0) red[tid >> 5] = s;
    __syncthreads();
    float mu = (red[0] + red[1] + red[2] + red[3]) * (1.0f / D_);
    float d0 = v0 - mu, d1 = v1 - mu, d2 = v2 - mu;
    float sq = d0 * d0 + d1 * d1 + d2 * d2;
    #pragma unroll
    for (int o = 16; o > 0; o >>= 1) sq += __shfl_xor_sync(0xffffffffu, sq, o);
    if ((tid & 31) == 0) red2[tid >> 5] = sq;
    __syncthreads();
    float var = (red2[0] + red2[1] + red2[2] + red2[3]) * (1.0f / D_);
    float rstd = rsqrtf(var + 1e-5f);
    float* orow = out + (size_t)row * D_;
    orow[tid]       = d0 * rstd * w[tid]       + b[tid];
    orow[tid + 128] = d1 * rstd * w[tid + 128] + b[tid + 128];
    orow[tid + 256] = d2 * rstd * w[tid + 256] + b[tid + 256];
}

// ======================= Pipelined TF32 GEMM, NT =======================
// C = alpha * A * W^T (+bias)(+gelu)(+residual); W selected by output-col segment.
// Block tile 128x128, BK=16, double-buffered cp.async. 8 warps, warp tile 64x32.
template <int ACT, bool BIAS, bool RES>
__global__ void __launch_bounds__(256) gemm_nt_tc(
    const float* __restrict__ A,
    const float* __restrict__ Wa, const float* __restrict__ Wb2,
    const float* __restrict__ Wc,
    const float* __restrict__ bias, const float* __restrict__ res,
    float* __restrict__ C,
    int K, int lda, int ldw, int ldc, int nseg, float alpha) {
    constexpr int SS = 20;
    __shared__ float sA[2][128 * SS];
    __shared__ float sW[2][128 * SS];

    int tid = threadIdx.x, lane = tid & 31, wid = tid >> 5;
    int wm = wid & 1, wn = wid >> 1;
    int g = lane >> 2, t = lane & 3;
    int m0 = blockIdx.y * 128;
    int n0g = blockIdx.x * 128;
    int seg = n0g / nseg;
    const float* W = (seg == 0) ? Wa : ((seg == 1) ? Wb2 : Wc);
    int n0 = n0g - seg * nseg;

    // per-thread staging coordinates: rows (r, r+64), cols c4..c4+3
    int r = tid >> 2, c4 = (tid & 3) * 4;
    const float* Ap = A + (size_t)(m0 + r) * lda + c4;
    const float* Wp = W + (size_t)(n0 + r) * ldw + c4;
    float* dA0 = &sA[0][r * SS + c4];
    float* dW0 = &sW[0][r * SS + c4];

    float acc[4][4][4] = {};

    // prologue: stage 0
    cp16(dA0, Ap);
    cp16(dA0 + 64 * SS, Ap + (size_t)64 * lda);
    cp16(dW0, Wp);
    cp16(dW0 + 64 * SS, Wp + (size_t)64 * ldw);
    asm volatile("cp.async.commit_group;");

    int stage = 0;
    for (int k0 = 0; k0 < K; k0 += 16) {
        if (k0 + 16 < K) {
            int st = stage ^ 1;
            float* dA = &sA[st][r * SS + c4];
            float* dW = &sW[st][r * SS + c4];
            cp16(dA, Ap + k0 + 16);
            cp16(dA + 64 * SS, Ap + (size_t)64 * lda + k0 + 16);
            cp16(dW, Wp + k0 + 16);
            cp16(dW + 64 * SS, Wp + (size_t)64 * ldw + k0 + 16);
            asm volatile("cp.async.commit_group;");
            asm volatile("cp.async.wait_group 1;");
        } else {
            asm volatile("cp.async.wait_group 0;");
        }
        __syncthreads();

        const float* cA = sA[stage];
        const float* cW = sW[stage];
        #pragma unroll
        for (int ks = 0; ks < 16; ks += 8) {
            unsigned a[4][4], b[4][2];
            #pragma unroll
            for (int mf = 0; mf < 4; mf++) {
                const float* p = cA + (wm * 64 + mf * 16 + g) * SS + ks + t;
                a[mf][0] = f2tf32(p[0]);
                a[mf][1] = f2tf32(p[8 * SS]);
                a[mf][2] = f2tf32(p[4]);
                a[mf][3] = f2tf32(p[8 * SS + 4]);
            }
            #pragma unroll
            for (int nf = 0; nf < 4; nf++) {
                const float* p = cW + (wn * 32 + nf * 8 + g) * SS + ks + t;
                b[nf][0] = f2tf32(p[0]);
                b[nf][1] = f2tf32(p[4]);
            }
            #pragma unroll
            for (int mf = 0; mf < 4; mf++)
                #pragma unroll
                for (int nf = 0; nf < 4; nf++)
                    mma_tf32(acc[mf][nf], a[mf][0], a[mf][1], a[mf][2], a[mf][3],
                             b[nf][0], b[nf][1]);
        }
        __syncthreads();
        stage ^= 1;
    }

    // ---- epilogue ----
    #pragma unroll
    for (int mf = 0; mf < 4; mf++) {
        int r0 = m0 + wm * 64 + mf * 16 + g;
        #pragma unroll
        for (int nf = 0; nf < 4; nf++) {
            int c = n0g + wn * 32 + nf * 8 + 2 * t;
            float v0 = acc[mf][nf][0] * alpha, v1 = acc[mf][nf][1] * alpha;
            float v2 = acc[mf][nf][2] * alpha, v3 = acc[mf][nf][3] * alpha;
            if (BIAS) {
                float b0v = bias[c], b1v = bias[c + 1];
                v0 += b0v; v1 += b1v; v2 += b0v; v3 += b1v;
            }
            if (ACT == 1) {
                v0 = gelu_exact(v0); v1 = gelu_exact(v1);
                v2 = gelu_exact(v2); v3 = gelu_exact(v3);
            }
            if (RES) {
                v0 += res[(size_t)r0 * ldc + c];
                v1 += res[(size_t)r0 * ldc + c + 1];
                v2 += res[(size_t)(r0 + 8) * ldc + c];
                v3 += res[(size_t)(r0 + 8) * ldc + c + 1];
            }
            *(float2*)(C + (size_t)r0 * ldc + c)       = make_float2(v0, v1);
            *(float2*)(C + (size_t)(r0 + 8) * ldc + c) = make_float2(v2, v3);
        }
    }
}

// ======================= Flash attention (fused QK^T + softmax + PV) =======================
// One block: 128 q rows x one (b,h). Loops over 8 kv tiles of 128.
// S-mma warp layout: wms=wid&1 (64 m), wns=wid>>1 (32 n).
// PV warp layout:    wmo=wid&3 (32 m), wno=wid>>2 (32 n).
#define FA_SQ   0                       // 128*68 u32
#define FA_SK   (128 * 68)              // 128*68 u32
#define FA_SV   (FA_SK + 128 * 68)      // 128*72 u32
#define FA_SP   (FA_SV + 128 * 72)      // 128*132 u32
#define FA_RED  (FA_SP + 128 * 132)     // 512 f32
#define FA_M    (FA_RED + 512)          // 128
#define FA_L    (FA_M + 128)            // 128
#define FA_F    (FA_L + 128)            // 128
#define FA_WORDS (FA_F + 128)

__global__ void __launch_bounds__(256, 1) flash_attn(const float* __restrict__ qkv,
                                                     float* __restrict__ o_out) {
    extern __shared__ unsigned smem[];
    unsigned* sQ = smem + FA_SQ;
    unsigned* sK = smem + FA_SK;
    unsigned* sV = smem + FA_SV;
    unsigned* sP = smem + FA_SP;
    float* rred  = (float*)(smem + FA_RED);
    float* m_run = (float*)(smem + FA_M);
    float* l_run = (float*)(smem + FA_L);
    float* fcor  = (float*)(smem + FA_F);

    int tid = threadIdx.x, lane = tid & 31, wid = tid >> 5;
    int g = lane >> 2, t = lane & 3;
    int bh = blockIdx.y;
    int b = bh / H_, h = bh % H_;
    int q0 = blockIdx.x * 128;
    const float* qb = qkv + (size_t)b * N_ * 1152 + h * 64;
    const float* kb = qb + 384;
    const float* vb = qb + 768;

    // load Q tile [128 x 64] (tf32)
    #pragma unroll
    for (int idx = tid; idx < 2048; idx += 256) {
        int rr = idx >> 4, c4 = (idx & 15) * 4;
        float4 v = *(const float4*)(qb + (size_t)(q0 + rr) * 1152 + c4);
        unsigned* d = sQ + rr * 68 + c4;
        d[0] = f2tf32(v.x); d[1] = f2tf32(v.y); d[2] = f2tf32(v.z); d[3] = f2tf32(v.w);
    }
    if (tid < 128) { m_run[tid] = -1e30f; l_run[tid] = 0.f; }

    int wms = wid & 1, wns = wid >> 1;
    int wmo = wid & 3, wno = wid >> 2;
    float o_acc[2][4][4] = {};
    __syncthreads();

    for (int j = 0; j < 8; j++) {
        // load K,V tile j
        #pragma unroll
        for (int idx = tid; idx < 2048; idx += 256) {
            int rr = idx >> 4, c4 = (idx & 15) * 4;
            float4 kv4 = *(const float4*)(kb + (size_t)(j * 128 + rr) * 1152 + c4);
            unsigned* d = sK + rr * 68 + c4;
            d[0] = f2tf32(kv4.x); d[1] = f2tf32(kv4.y);
            d[2] = f2tf32(kv4.z); d[3] = f2tf32(kv4.w);
            float4 vv = *(const float4*)(vb + (size_t)(j * 128 + rr) * 1152 + c4);
            unsigned* dv = sV + rr * 72 + c4;
            dv[0] = f2tf32(vv.x); dv[1] = f2tf32(vv.y);
            dv[2] = f2tf32(vv.z); dv[3] = f2tf32(vv.w);
        }
        __syncthreads();

        // ---- S = Q K^T ----
        float s[4][4][4] = {};
        #pragma unroll
        for (int ks = 0; ks < 64; ks += 8) {
            unsigned a[4][4], bb[4][2];
            #pragma unroll
            for (int mf = 0; mf < 4; mf++) {
                const unsigned* p = sQ + (wms * 64 + mf * 16 + g) * 68 + ks + t;
                a[mf][0] = p[0]; a[mf][1] = p[8 * 68];
                a[mf][2] = p[4]; a[mf][3] = p[8 * 68 + 4];
            }
            #pragma unroll
            for (int nf = 0; nf < 4; nf++) {
                const unsigned* p = sK + (wns * 32 + nf * 8 + g) * 68 + ks + t;
                bb[nf][0] = p[0]; bb[nf][1] = p[4];
            }
            #pragma unroll
            for (int mf = 0; mf < 4; mf++)
                #pragma unroll
                for (int nf = 0; nf < 4; nf++)
                    mma_tf32(s[mf][nf], a[mf][0], a[mf][1], a[mf][2], a[mf][3],
                             bb[nf][0], bb[nf][1]);
        }
        #pragma unroll
        for (int mf = 0; mf < 4; mf++)
            #pragma unroll
            for (int nf = 0; nf < 4; nf++)
                #pragma unroll
                for (int q = 0; q < 4; q++) s[mf][nf][q] *= 0.125f;

        // ---- row max (local -> shfl over t -> smem per wns) ----
        #pragma unroll
        for (int mf = 0; mf < 4; mf++) {
            float l0 = -1e30f, l1 = -1e30f;
            #pragma unroll
            for (int nf = 0; nf < 4; nf++) {
                l0 = fmaxf(l0, fmaxf(s[mf][nf][0], s[mf][nf][1]));
                l1 = fmaxf(l1, fmaxf(s[mf][nf][2], s[mf][nf][3]));
            }
            l0 = fmaxf(l0, __shfl_xor_sync(0xffffffffu, l0, 1));
            l0 = fmaxf(l0, __shfl_xor_sync(0xffffffffu, l0, 2));
            l1 = fmaxf(l1, __shfl_xor_sync(0xffffffffu, l1, 1));
            l1 = fmaxf(l1, __shfl_xor_sync(0xffffffffu, l1, 2));
            if (t == 0) {
                int r0 = wms * 64 + mf * 16 + g;
                rred[wns * 128 + r0]     = l0;
                rred[wns * 128 + r0 + 8] = l1;
            }
        }
        __syncthreads();
        if (tid < 128) {
            float mx = fmaxf(fmaxf(rred[tid], rred[128 + tid]),
                             fmaxf(rred[256 + tid], rred[384 + tid]));
            float mo = m_run[tid];
            float mn = fmaxf(mo, mx);
            m_run[tid] = mn;
            fcor[tid] = __expf(mo - mn);
        }
        __syncthreads();

        // ---- P = exp(s - m): store to sP, accumulate row sums ----
        #pragma unroll
        for (int mf = 0; mf < 4; mf++) {
            int r0 = wms * 64 + mf * 16 + g;
            float m0v = m_run[r0], m1v = m_run[r0 + 8];
            float ls0 = 0.f, ls1 = 0.f;
            #pragma unroll
            for (int nf = 0; nf < 4; nf++) {
                int c = wns * 32 + nf * 8 + 2 * t;
                float p0 = __expf(s[mf][nf][0] - m0v);
                float p1 = __expf(s[mf][nf][1] - m0v);
                float p2 = __expf(s[mf][nf][2] - m1v);
                float p3 = __expf(s[mf][nf][3] - m1v);
                sP[r0 * 132 + c]           = f2tf32(p0);
                sP[r0 * 132 + c + 1]       = f2tf32(p1);
                sP[(r0 + 8) * 132 + c]     = f2tf32(p2);
                sP[(r0 + 8) * 132 + c + 1] = f2tf32(p3);
                ls0 += p0 + p1; ls1 += p2 + p3;
            }
            ls0 += __shfl_xor_sync(0xffffffffu, ls0, 1);
            ls0 += __shfl_xor_sync(0xffffffffu, ls0, 2);
            ls1 += __shfl_xor_sync(0xffffffffu, ls1, 1);
            ls1 += __shfl_xor_sync(0xffffffffu, ls1, 2);
            if (t == 0) {
                rred[wns * 128 + r0]     = ls0;
                rred[wns * 128 + r0 + 8] = ls1;
            }
        }
        __syncthreads();
        if (tid < 128)
            l_run[tid] = l_run[tid] * fcor[tid] +
                         rred[tid] + rred[128 + tid] + rred[256 + tid] + rred[384 + tid];

        // ---- rescale O accumulator ----
        #pragma unroll
        for (int mf2 = 0; mf2 < 2; mf2++) {
            int rr = wmo * 32 + mf2 * 16 + g;
            float f0 = fcor[rr], f1 = fcor[rr + 8];
            #pragma unroll
            for (int nf = 0; nf < 4; nf++) {
                o_acc[mf2][nf][0] *= f0; o_acc[mf2][nf][1] *= f0;
                o_acc[mf2][nf][2] *= f1; o_acc[mf2][nf][3] *= f1;
            }
        }

        // ---- O += P V ----
        #pragma unroll
        for (int ks2 = 0; ks2 < 128; ks2 += 8) {
            unsigned a[2][4], bb[4][2];
            #pragma unroll
            for (int mf2 = 0; mf2 < 2; mf2++) {
                const unsigned* p = sP + (wmo * 32 + mf2 * 16 + g) * 132 + ks2 + t;
                a[mf2][0] = p[0]; a[mf2][1] = p[8 * 132];
                a[mf2][2] = p[4]; a[mf2][3] = p[8 * 132 + 4];
            }
            #pragma unroll
            for (int nf = 0; nf < 4; nf++) {
                int n = wno * 32 + nf * 8 + g;
                bb[nf][0] = sV[(ks2 + t) * 72 + n];
                bb[nf][1] = sV[(ks2 + t + 4) * 72 + n];
            }
            #pragma unroll
            for (int mf2 = 0; mf2 < 2; mf2++)
                #pragma unroll
                for (int nf = 0; nf < 4; nf++)
                    mma_tf32(o_acc[mf2][nf], a[mf2][0], a[mf2][1], a[mf2][2], a[mf2][3],
                             bb[nf][0], bb[nf][1]);
        }
        __syncthreads();
    }

    // ---- epilogue: O / l ----
    #pragma unroll
    for (int mf2 = 0; mf2 < 2; mf2++) {
        int rr = wmo * 32 + mf2 * 16 + g;
        float inv0 = 1.0f / l_run[rr], inv1 = 1.0f / l_run[rr + 8];
        size_t row0 = (size_t)(b * N_ + q0 + rr) * D_ + h * 64;
        size_t row1 = row0 + (size_t)8 * D_;
        #pragma unroll
        for (int nf = 0; nf < 4; nf++) {
            int cl = wno * 32 + nf * 8 + 2 * t;
            *(float2*)(o_out + row0 + cl) =
                make_float2(o_acc[mf2][nf][0] * inv0, o_acc[mf2][nf][1] * inv0);
            *(float2*)(o_out + row1 + cl) =
                make_float2(o_acc[mf2][nf][2] * inv1, o_acc[mf2][nf][3] * inv1);
        }
    }
}

// ---------------- launch ----------------
extern "C" void kernel_launch(void* const* d_in, const int* in_sizes, int n_in,
                              void* d_out, int out_size) {
    const float* X    = (const float*)d_in[0];
    const float* Wq   = (const float*)d_in[1];
    const float* Wk   = (const float*)d_in[2];
    const float* Wv   = (const float*)d_in[3];
    const float* Wo   = (const float*)d_in[4];
    const float* bo   = (const float*)d_in[5];
    const float* ln1w = (const float*)d_in[6];
    const float* ln1b = (const float*)d_in[7];
    const float* ln2w = (const float*)d_in[8];
    const float* ln2b = (const float*)d_in[9];
    const float* W1   = (const float*)d_in[10];
    const float* b1   = (const float*)d_in[11];
    const float* W2   = (const float*)d_in[12];
    const float* b2   = (const float*)d_in[13];
    float* out = (float*)d_out;

    float *t, *qkv, *o, *y, *x2, *h;
    cudaGetSymbolAddress((void**)&t,   g_t);
    cudaGetSymbolAddress((void**)&qkv, g_qkv);
    cudaGetSymbolAddress((void**)&o,   g_o);
    cudaGetSymbolAddress((void**)&y,   g_y);
    cudaGetSymbolAddress((void**)&x2,  g_x2);
    cudaGetSymbolAddress((void**)&h,   g_h);

    const int fa_smem = FA_WORDS * 4;
    cudaFuncSetAttribute(flash_attn, cudaFuncAttributeMaxDynamicSharedMemorySize, fa_smem);

    // 1) LN1
    ln_kernel<<<MTOK, 128>>>(X, ln1w, ln1b, t);

    // 2) fused QKV projection: qkv[:, 0:384]=Q, [384:768]=K, [768:1152]=V
    {
        dim3 gsz(9, 128);
        gemm_nt_tc<0, false, false><<<gsz, 256>>>(t, Wq, Wk, Wv, nullptr, nullptr, qkv,
            D_, D_, D_, 3 * D_, 384, 1.0f);
    }

    // 3) flash attention -> g_o [MTOK, 384] head-concat
    {
        dim3 gsz(8, B_ * H_);
        flash_attn<<<gsz, 256, fa_smem>>>(qkv, o);
    }

    // 4) y = X + (o @ Wo^T + bo)
    {
        dim3 gsz(3, 128);
        gemm_nt_tc<0, true, true><<<gsz, 256>>>(o, Wo, Wo, Wo, bo, X, y,
            D_, D_, D_, D_, 1 << 30, 1.0f);
    }

    // 5) LN2
    ln_kernel<<<MTOK, 128>>>(y, ln2w, ln2b, x2);

    // 6) h = gelu(x2 @ W1^T + b1)
    {
        dim3 gsz(6, 128);
        gemm_nt_tc<1, true, false><<<gsz, 256>>>(x2, W1, W1, W1, b1, nullptr, h,
            D_, D_, D_, 2 * D_, 1 << 30, 1.0f);
    }

    // 7) out = x2 + (h @ W2^T + b2)
    {
        dim3 gsz(3, 128);
        gemm_nt_tc<0, true, true><<<gsz, 256>>>(h, W2, W2, W2, b2, x2, out,
            2 * D_, 2 * D_, 2 * D_, D_, 1 << 30, 1.0f);
    }
}

// round 4
// speedup vs baseline: 6.8002x; 1.9975x over previous
#include <cuda_runtime.h>
#include <cuda_fp16.h>
#include <cmath>

#define B_   16
#define N_   1024
#define D_   384
#define H_   6
#define DH_  64
#define MTOK (B_ * N_)

// ---------------- scratch (device globals) ----------------
__device__ __half g_wh[1179648];                 // all weights, half
__device__ __half g_t_h[MTOK * D_];              // LN1 out (half)
__device__ __half g_qkv_h[MTOK * 3 * D_];        // q|k|v per token (half)
__device__ __half g_o_h[MTOK * D_];              // attention out (half)
__device__ __half g_x2_h[MTOK * D_];             // LN2 out (half)
__device__ __half g_h_h[MTOK * 2 * D_];          // MLP hidden (half)
__device__ float  g_y[MTOK * D_];                // X + attn (fp32)
__device__ float  g_x2f[MTOK * D_];              // LN2 out (fp32, residual)

// weight offsets in g_wh
#define WOFF_Q  0
#define WOFF_K  147456
#define WOFF_V  294912
#define WOFF_O  442368
#define WOFF_1  589824
#define WOFF_2  884736

__device__ __forceinline__ float gelu_exact(float x) {
    return 0.5f * x * (1.0f + erff(x * 0.7071067811865475f));
}
__device__ __forceinline__ unsigned scvt(const void* p) {
    return (unsigned)__cvta_generic_to_shared(p);
}
__device__ __forceinline__ unsigned pack2(float a, float b) {
    __half2 h = __floats2half2_rn(a, b);
    return *reinterpret_cast<unsigned*>(&h);
}
__device__ __forceinline__ void mma_f16(float* c, unsigned a0, unsigned a1,
                                        unsigned a2, unsigned a3,
                                        unsigned b0, unsigned b1) {
    asm volatile(
        "mma.sync.aligned.m16n8k16.row.col.f32.f16.f16.f32 "
        "{%0,%1,%2,%3}, {%4,%5,%6,%7}, {%8,%9}, {%0,%1,%2,%3};\n"
        : "+f"(c[0]), "+f"(c[1]), "+f"(c[2]), "+f"(c[3])
        : "r"(a0), "r"(a1), "r"(a2), "r"(a3), "r"(b0), "r"(b1));
}
__device__ __forceinline__ void ldm_x4(unsigned* r, unsigned addr) {
    asm volatile("ldmatrix.sync.aligned.m8n8.x4.shared.b16 {%0,%1,%2,%3}, [%4];"
                 : "=r"(r[0]), "=r"(r[1]), "=r"(r[2]), "=r"(r[3]) : "r"(addr));
}
__device__ __forceinline__ void ldm_x4t(unsigned* r, unsigned addr) {
    asm volatile("ldmatrix.sync.aligned.m8n8.x4.trans.shared.b16 {%0,%1,%2,%3}, [%4];"
                 : "=r"(r[0]), "=r"(r[1]), "=r"(r[2]), "=r"(r[3]) : "r"(addr));
}
__device__ __forceinline__ void cp16(void* s, const void* g) {
    unsigned sa = scvt(s);
    asm volatile("cp.async.ca.shared.global [%0], [%1], 16;" :: "r"(sa), "l"(g));
}

// ---------------- weight fp32 -> fp16 ----------------
__global__ void f2h_kernel(const float* __restrict__ s, __half* __restrict__ d, int n) {
    int i = blockIdx.x * 256 + threadIdx.x;
    if (i < n) d[i] = __float2half(s[i]);
}

// ---------------- LayerNorm (row D=384) -> half (+optional fp32) ----------------
template <bool DUAL>
__global__ void ln_h(const float* __restrict__ x, const float* __restrict__ w,
                     const float* __restrict__ b, __half* __restrict__ outh,
                     float* __restrict__ outf) {
    int row = blockIdx.x;
    const float* xr = x + (size_t)row * D_;
    int tid = threadIdx.x;
    float v0 = xr[tid], v1 = xr[tid + 128], v2 = xr[tid + 256];
    float s = v0 + v1 + v2;
    __shared__ float red[4], red2[4];
    #pragma unroll
    for (int o = 16; o > 0; o >>= 1) s += __shfl_xor_sync(0xffffffffu, s, o);
    if ((tid & 31) == 0) red[tid >> 5] = s;
    __syncthreads();
    float mu = (red[0] + red[1] + red[2] + red[3]) * (1.0f / D_);
    float d0 = v0 - mu, d1 = v1 - mu, d2 = v2 - mu;
    float sq = d0 * d0 + d1 * d1 + d2 * d2;
    #pragma unroll
    for (int o = 16; o > 0; o >>= 1) sq += __shfl_xor_sync(0xffffffffu, sq, o);
    if ((tid & 31) == 0) red2[tid >> 5] = sq;
    __syncthreads();
    float var = (red2[0] + red2[1] + red2[2] + red2[3]) * (1.0f / D_);
    float rstd = rsqrtf(var + 1e-5f);
    float o0 = d0 * rstd * w[tid]       + b[tid];
    float o1 = d1 * rstd * w[tid + 128] + b[tid + 128];
    float o2 = d2 * rstd * w[tid + 256] + b[tid + 256];
    __half* oh = outh + (size_t)row * D_;
    oh[tid] = __float2half(o0); oh[tid + 128] = __float2half(o1); oh[tid + 256] = __float2half(o2);
    if (DUAL) {
        float* of = outf + (size_t)row * D_;
        of[tid] = o0; of[tid + 128] = o1; of[tid + 256] = o2;
    }
}

// ======================= fp16 tensor-core GEMM, NT =======================
// C = A(half,[M,K]) * W(half,[N,K])^T (+bias)(+gelu)(+res fp32); out half or fp32.
// BM=BN=128, BK=32, double-buffered cp.async, 8 warps (warp tile 64x32).
template <int ACT, bool BIAS, bool RES, bool OUTH>
__global__ void __launch_bounds__(256) gemm_h(
    const __half* __restrict__ A,
    const __half* __restrict__ Wa, const __half* __restrict__ Wb2,
    const __half* __restrict__ Wc,
    const float* __restrict__ bias, const float* __restrict__ res,
    __half* __restrict__ Ch, float* __restrict__ Cf,
    int K, int ldc, int nseg) {
    __shared__ __half sA[2][128 * 40];
    __shared__ __half sW[2][128 * 40];

    int tid = threadIdx.x, lane = tid & 31, wid = tid >> 5;
    int wm = wid & 1, wn = wid >> 1;
    int g = lane >> 2, t = lane & 3;
    int m0 = blockIdx.y * 128, n0g = blockIdx.x * 128;
    int seg = n0g / nseg;
    const __half* W = (seg == 0) ? Wa : ((seg == 1) ? Wb2 : Wc);
    int n0 = n0g - seg * nseg;

    int r1 = tid >> 2, c1 = (tid & 3) * 8;      // row, col(halves)
    const __half* Ap = A + (size_t)(m0 + r1) * K + c1;
    const __half* Wp = W + (size_t)(n0 + r1) * K + c1;

    unsigned aB0 = scvt(&sA[0][0]);
    unsigned wB0 = scvt(&sW[0][0]);
    int arow = lane & 15, asel = (lane & 16) ? 8 : 0;
    int brow = (lane & 7) + ((lane & 16) ? 8 : 0), bsel = (lane & 8) ? 8 : 0;
    unsigned aOff = ((wm * 64 + arow) * 40 + asel) * 2;
    unsigned wOff = ((wn * 32 + brow) * 40 + bsel) * 2;

    float acc[4][4][4] = {};

    // prologue stage 0
    {
        __half* dA = &sA[0][r1 * 40 + c1];
        cp16(dA, Ap); cp16(dA + 64 * 40, Ap + (size_t)64 * K);
        __half* dW = &sW[0][r1 * 40 + c1];
        cp16(dW, Wp); cp16(dW + 64 * 40, Wp + (size_t)64 * K);
        asm volatile("cp.async.commit_group;");
    }

    int nk = K / 32;
    for (int it = 0; it < nk; it++) {
        if (it + 1 < nk) {
            int st = (it + 1) & 1;
            int k0 = (it + 1) * 32;
            __half* dA = &sA[st][r1 * 40 + c1];
            cp16(dA, Ap + k0); cp16(dA + 64 * 40, Ap + (size_t)64 * K + k0);
            __half* dW = &sW[st][r1 * 40 + c1];
            cp16(dW, Wp + k0); cp16(dW + 64 * 40, Wp + (size_t)64 * K + k0);
            asm volatile("cp.async.commit_group;");
            asm volatile("cp.async.wait_group 1;");
        } else {
            asm volatile("cp.async.wait_group 0;");
        }
        __syncthreads();

        int st = it & 1;
        unsigned aBase = aB0 + st * 10240 + aOff;
        unsigned wBase = wB0 + st * 10240 + wOff;
        #pragma unroll
        for (int kc = 0; kc < 2; kc++) {
            unsigned a[4][4];
            #pragma unroll
            for (int mf = 0; mf < 4; mf++)
                ldm_x4(a[mf], aBase + mf * 16 * 80 + kc * 32);
            unsigned b[4][2];
            #pragma unroll
            for (int nfp = 0; nfp < 2; nfp++) {
                unsigned r[4];
                ldm_x4(r, wBase + nfp * 16 * 80 + kc * 32);
                b[2 * nfp][0] = r[0]; b[2 * nfp][1] = r[1];
                b[2 * nfp + 1][0] = r[2]; b[2 * nfp + 1][1] = r[3];
            }
            #pragma unroll
            for (int mf = 0; mf < 4; mf++)
                #pragma unroll
                for (int nf = 0; nf < 4; nf++)
                    mma_f16(acc[mf][nf], a[mf][0], a[mf][1], a[mf][2], a[mf][3],
                            b[nf][0], b[nf][1]);
        }
        __syncthreads();
    }

    // ---- epilogue ----
    #pragma unroll
    for (int mf = 0; mf < 4; mf++) {
        int r0 = m0 + wm * 64 + mf * 16 + g;
        #pragma unroll
        for (int nf = 0; nf < 4; nf++) {
            int c = n0g + wn * 32 + nf * 8 + 2 * t;
            float v0 = acc[mf][nf][0], v1 = acc[mf][nf][1];
            float v2 = acc[mf][nf][2], v3 = acc[mf][nf][3];
            if (BIAS) {
                float b0v = bias[c], b1v = bias[c + 1];
                v0 += b0v; v1 += b1v; v2 += b0v; v3 += b1v;
            }
            if (ACT == 1) {
                v0 = gelu_exact(v0); v1 = gelu_exact(v1);
                v2 = gelu_exact(v2); v3 = gelu_exact(v3);
            }
            if (RES) {
                v0 += res[(size_t)r0 * ldc + c];
                v1 += res[(size_t)r0 * ldc + c + 1];
                v2 += res[(size_t)(r0 + 8) * ldc + c];
                v3 += res[(size_t)(r0 + 8) * ldc + c + 1];
            }
            if (OUTH) {
                *(__half2*)(Ch + (size_t)r0 * ldc + c)       = __floats2half2_rn(v0, v1);
                *(__half2*)(Ch + (size_t)(r0 + 8) * ldc + c) = __floats2half2_rn(v2, v3);
            } else {
                *(float2*)(Cf + (size_t)r0 * ldc + c)       = make_float2(v0, v1);
                *(float2*)(Cf + (size_t)(r0 + 8) * ldc + c) = make_float2(v2, v3);
            }
        }
    }
}

// ======================= fp16 flash attention =======================
// Block: 64 q rows (4 warps x 16 rows), one (b,h). 8 kv tiles of 128.
// Softmax fully warp-local; P stays in registers (C->A fragment reuse).
#define FQ_STR 72
#define FKV_HALF 9216     // 128*72

__global__ void __launch_bounds__(128) flash_h(const __half* __restrict__ qkv,
                                               __half* __restrict__ o_out) {
    extern __shared__ __half fsm[];
    __half* sQ = fsm;                       // 64*72
    __half* sK = fsm + 64 * FQ_STR;         // 2 * 128*72
    __half* sV = sK + 2 * FKV_HALF;         // 2 * 128*72

    int tid = threadIdx.x, lane = tid & 31, wid = tid >> 5;
    int g = lane >> 2, t = lane & 3;
    int bh = blockIdx.y, b = bh / H_, h = bh % H_;
    int q0 = blockIdx.x * 64;
    const __half* qb = qkv + (size_t)b * N_ * 1152 + h * 64;
    const __half* kb = qb + 384;
    const __half* vb = qb + 768;

    // stage Q (group 0, together with K0/V0)
    #pragma unroll
    for (int i = 0; i < 4; i++) {
        int id = tid + i * 128, row = id >> 3, cg = (id & 7) * 8;
        cp16(&sQ[row * FQ_STR + cg], qb + (size_t)(q0 + row) * 1152 + cg);
    }
    // stage K0,V0
    #pragma unroll
    for (int i = 0; i < 8; i++) {
        int id = tid + i * 128, row = id >> 3, cg = (id & 7) * 8;
        cp16(&sK[row * FQ_STR + cg], kb + (size_t)row * 1152 + cg);
        cp16(&sV[row * FQ_STR + cg], vb + (size_t)row * 1152 + cg);
    }
    asm volatile("cp.async.commit_group;");

    unsigned qB = scvt(sQ), kB = scvt(sK), vB = scvt(sV);
    int arow = lane & 15, asel = (lane & 16) ? 8 : 0;
    int brow = (lane & 7) + ((lane & 16) ? 8 : 0), bsel = (lane & 8) ? 8 : 0;
    unsigned qAddr  = qB + ((16 * wid + arow) * FQ_STR + asel) * 2;
    unsigned kAddr0 = kB + (brow * FQ_STR + bsel) * 2;
    unsigned vAddr0 = vB + (arow * FQ_STR + asel) * 2;

    float m0 = -1e30f, m1 = -1e30f, l0 = 0.f, l1 = 0.f;
    float o[8][4] = {};

    for (int j = 0; j < 8; j++) {
        if (j < 7) {
            __half* dK = sK + ((j + 1) & 1) * FKV_HALF;
            __half* dV = sV + ((j + 1) & 1) * FKV_HALF;
            const __half* kg = kb + (size_t)(j + 1) * 128 * 1152;
            const __half* vg = vb + (size_t)(j + 1) * 128 * 1152;
            #pragma unroll
            for (int i = 0; i < 8; i++) {
                int id = tid + i * 128, row = id >> 3, cg = (id & 7) * 8;
                cp16(&dK[row * FQ_STR + cg], kg + (size_t)row * 1152 + cg);
                cp16(&dV[row * FQ_STR + cg], vg + (size_t)row * 1152 + cg);
            }
            asm volatile("cp.async.commit_group;");
            asm volatile("cp.async.wait_group 1;");
        } else {
            asm volatile("cp.async.wait_group 0;");
        }
        __syncthreads();

        unsigned kA = kAddr0 + (j & 1) * (FKV_HALF * 2);
        unsigned vA = vAddr0 + (j & 1) * (FKV_HALF * 2);

        // ---- S = Q K^T (per warp: 16 rows x 128 cols) ----
        float sc[16][4];
        #pragma unroll
        for (int nf = 0; nf < 16; nf++)
            sc[nf][0] = sc[nf][1] = sc[nf][2] = sc[nf][3] = 0.f;
        #pragma unroll
        for (int kc = 0; kc < 4; kc++) {
            unsigned aq[4];
            ldm_x4(aq, qAddr + kc * 32);
            #pragma unroll
            for (int nfp = 0; nfp < 8; nfp++) {
                unsigned bk[4];
                ldm_x4(bk, kA + nfp * 16 * (FQ_STR * 2) + kc * 32);
                mma_f16(sc[2 * nfp],     aq[0], aq[1], aq[2], aq[3], bk[0], bk[1]);
                mma_f16(sc[2 * nfp + 1], aq[0], aq[1], aq[2], aq[3], bk[2], bk[3]);
            }
        }

        // ---- warp-local online softmax (scale 0.125 folded into exp) ----
        float mx0 = -1e30f, mx1 = -1e30f;
        #pragma unroll
        for (int nf = 0; nf < 16; nf++) {
            mx0 = fmaxf(mx0, fmaxf(sc[nf][0], sc[nf][1]));
            mx1 = fmaxf(mx1, fmaxf(sc[nf][2], sc[nf][3]));
        }
        mx0 = fmaxf(mx0, __shfl_xor_sync(0xffffffffu, mx0, 1));
        mx0 = fmaxf(mx0, __shfl_xor_sync(0xffffffffu, mx0, 2));
        mx1 = fmaxf(mx1, __shfl_xor_sync(0xffffffffu, mx1, 1));
        mx1 = fmaxf(mx1, __shfl_xor_sync(0xffffffffu, mx1, 2));
        float mn0 = fmaxf(m0, mx0), mn1 = fmaxf(m1, mx1);
        float f0 = __expf((m0 - mn0) * 0.125f);
        float f1 = __expf((m1 - mn1) * 0.125f);
        m0 = mn0; m1 = mn1;

        float ls0 = 0.f, ls1 = 0.f;
        unsigned ph[16][2];
        #pragma unroll
        for (int nf = 0; nf < 16; nf++) {
            float p0 = __expf((sc[nf][0] - mn0) * 0.125f);
            float p1 = __expf((sc[nf][1] - mn0) * 0.125f);
            float p2 = __expf((sc[nf][2] - mn1) * 0.125f);
            float p3 = __expf((sc[nf][3] - mn1) * 0.125f);
            ls0 += p0 + p1; ls1 += p2 + p3;
            ph[nf][0] = pack2(p0, p1);
            ph[nf][1] = pack2(p2, p3);
        }
        ls0 += __shfl_xor_sync(0xffffffffu, ls0, 1);
        ls0 += __shfl_xor_sync(0xffffffffu, ls0, 2);
        ls1 += __shfl_xor_sync(0xffffffffu, ls1, 1);
        ls1 += __shfl_xor_sync(0xffffffffu, ls1, 2);
        l0 = l0 * f0 + ls0;
        l1 = l1 * f1 + ls1;

        #pragma unroll
        for (int nf2 = 0; nf2 < 8; nf2++) {
            o[nf2][0] *= f0; o[nf2][1] *= f0;
            o[nf2][2] *= f1; o[nf2][3] *= f1;
        }

        // ---- O += P V (A frags straight from registers) ----
        #pragma unroll
        for (int kc2 = 0; kc2 < 8; kc2++) {
            unsigned a0 = ph[2 * kc2][0], a1 = ph[2 * kc2][1];
            unsigned a2 = ph[2 * kc2 + 1][0], a3 = ph[2 * kc2 + 1][1];
            #pragma unroll
            for (int nfq = 0; nfq < 4; nfq++) {
                unsigned bv[4];
                ldm_x4t(bv, vA + kc2 * 16 * (FQ_STR * 2) + nfq * 32);
                mma_f16(o[2 * nfq],     a0, a1, a2, a3, bv[0], bv[1]);
                mma_f16(o[2 * nfq + 1], a0, a1, a2, a3, bv[2], bv[3]);
            }
        }
        __syncthreads();
    }

    // ---- epilogue ----
    float i0 = 1.0f / l0, i1 = 1.0f / l1;
    size_t tok0 = (size_t)(b * N_ + q0 + 16 * wid + g);
    __half* out0 = o_out + tok0 * D_ + h * 64;
    __half* out1 = out0 + (size_t)8 * D_;
    #pragma unroll
    for (int nf2 = 0; nf2 < 8; nf2++) {
        int c = nf2 * 8 + 2 * t;
        *(__half2*)(out0 + c) = __floats2half2_rn(o[nf2][0] * i0, o[nf2][1] * i0);
        *(__half2*)(out1 + c) = __floats2half2_rn(o[nf2][2] * i1, o[nf2][3] * i1);
    }
}

// ---------------- launch ----------------
extern "C" void kernel_launch(void* const* d_in, const int* in_sizes, int n_in,
                              void* d_out, int out_size) {
    const float* X    = (const float*)d_in[0];
    const float* Wq   = (const float*)d_in[1];
    const float* Wk   = (const float*)d_in[2];
    const float* Wv   = (const float*)d_in[3];
    const float* Wo   = (const float*)d_in[4];
    const float* bo   = (const float*)d_in[5];
    const float* ln1w = (const float*)d_in[6];
    const float* ln1b = (const float*)d_in[7];
    const float* ln2w = (const float*)d_in[8];
    const float* ln2b = (const float*)d_in[9];
    const float* W1   = (const float*)d_in[10];
    const float* b1   = (const float*)d_in[11];
    const float* W2   = (const float*)d_in[12];
    const float* b2   = (const float*)d_in[13];
    float* out = (float*)d_out;

    __half *wh, *t_h, *qkv_h, *o_h, *x2_h, *h_h;
    float *y, *x2f;
    cudaGetSymbolAddress((void**)&wh,    g_wh);
    cudaGetSymbolAddress((void**)&t_h,   g_t_h);
    cudaGetSymbolAddress((void**)&qkv_h, g_qkv_h);
    cudaGetSymbolAddress((void**)&o_h,   g_o_h);
    cudaGetSymbolAddress((void**)&x2_h,  g_x2_h);
    cudaGetSymbolAddress((void**)&h_h,   g_h_h);
    cudaGetSymbolAddress((void**)&y,     g_y);
    cudaGetSymbolAddress((void**)&x2f,   g_x2f);

    const int fa_smem = (64 * FQ_STR + 4 * FKV_HALF) * 2;   // 82944 B
    cudaFuncSetAttribute(flash_h, cudaFuncAttributeMaxDynamicSharedMemorySize, fa_smem);

    // 0) weights -> half
    f2h_kernel<<<576, 256>>>(Wq, wh + WOFF_Q, 147456);
    f2h_kernel<<<576, 256>>>(Wk, wh + WOFF_K, 147456);
    f2h_kernel<<<576, 256>>>(Wv, wh + WOFF_V, 147456);
    f2h_kernel<<<576, 256>>>(Wo, wh + WOFF_O, 147456);
    f2h_kernel<<<1152, 256>>>(W1, wh + WOFF_1, 294912);
    f2h_kernel<<<1152, 256>>>(W2, wh + WOFF_2, 294912);

    // 1) LN1 -> half
    ln_h<false><<<MTOK, 128>>>(X, ln1w, ln1b, t_h, nullptr);

    // 2) fused QKV projection -> qkv_h [tok][1152]
    {
        dim3 gsz(9, 128);
        gemm_h<0, false, false, true><<<gsz, 256>>>(t_h,
            wh + WOFF_Q, wh + WOFF_K, wh + WOFF_V,
            nullptr, nullptr, qkv_h, nullptr, D_, 3 * D_, 384);
    }

    // 3) flash attention -> o_h
    {
        dim3 gsz(16, B_ * H_);
        flash_h<<<gsz, 128, fa_smem>>>(qkv_h, o_h);
    }

    // 4) y = X + (o @ Wo^T + bo)   (fp32 out)
    {
        dim3 gsz(3, 128);
        gemm_h<0, true, true, false><<<gsz, 256>>>(o_h,
            wh + WOFF_O, wh + WOFF_O, wh + WOFF_O,
            bo, X, nullptr, y, D_, D_, 1 << 30);
    }

    // 5) LN2 -> half + fp32
    ln_h<true><<<MTOK, 128>>>(y, ln2w, ln2b, x2_h, x2f);

    // 6) h = gelu(x2 @ W1^T + b1) -> half
    {
        dim3 gsz(6, 128);
        gemm_h<1, true, false, true><<<gsz, 256>>>(x2_h,
            wh + WOFF_1, wh + WOFF_1, wh + WOFF_1,
            b1, nullptr, h_h, nullptr, D_, 2 * D_, 1 << 30);
    }

    // 7) out = x2f + (h @ W2^T + b2)   (fp32 out)
    {
        dim3 gsz(3, 128);
        gemm_h<0, true, true, false><<<gsz, 256>>>(h_h,
            wh + WOFF_2, wh + WOFF_2, wh + WOFF_2,
            b2, x2f, nullptr, out, 2 * D_, D_, 1 << 30);
    }
}